// round 4
// baseline (speedup 1.0000x reference)
#include <cuda_runtime.h>

// PairWiseRankingLoss, closed form.
// gama=1, p=sigmoid(x) in (0,1)  =>  1 + p_i - p_j > 0 for every pair, so relu
// never clips and the masked pair-sum factorizes per row:
//   loss_b = n0*n1*gama + n1*sum_{y=0} p - n0*sum_{y=1} p
// Total = sum_b loss_b.
//
// 16 CTAs x 1024 threads, 8 rows per CTA (4 warps per row, 8 elems per thread).
// Cross-block: relaxed float atomicAdd into g_accum, then acq_rel ticket atomic
// (no MEMBAR). Last ticket holder does acquire-load of g_accum, writes out,
// plain-store rearms both globals for the next graph replay.

#define B_ROWS    128
#define L_COLS    1024
#define NBLOCKS   16
#define NTHREADS  1024
#define ROWS_PER_CTA 8   // 32 warps / 4 warps-per-row

__device__ float g_accum;           // zero at load; rearmed by last block each launch
__device__ unsigned int g_ticket;   // zero at load; rearmed by last block each launch

__device__ __forceinline__ float sigm(float x) {
    return 1.f / (1.f + __expf(-x));
}

__global__ void __launch_bounds__(NTHREADS)
prl_kernel(const float* __restrict__ logit,
           const int*   __restrict__ y,
           float*       __restrict__ out)
{
    const int t   = threadIdx.x;
    const int w   = t >> 5;          // warp 0..31
    const int lid = t & 31;
    const int row_in_cta = w >> 2;   // 0..7
    const int warp_in_row = w & 3;   // 0..3

    const int row  = blockIdx.x * ROWS_PER_CTA + row_in_cta;
    const int base = row * L_COLS + (warp_in_row * 32 + lid) * 8;

    // 8 consecutive elements per thread: 2x LDG.128 float + 2x LDG.128 int (MLP=4).
    const float4 l0 = *reinterpret_cast<const float4*>(logit + base);
    const float4 l1 = *reinterpret_cast<const float4*>(logit + base + 4);
    const int4   y0 = *reinterpret_cast<const int4*>(y + base);
    const int4   y1 = *reinterpret_cast<const int4*>(y + base + 4);

    // sum_all = sum p, sum_pos = sum y*p, cnt = sum y (float, exact).
    float sa = 0.f, sp = 0.f, c = 0.f;
    {
        float p;
        p = sigm(l0.x); sa += p; sp = fmaf((float)y0.x, p, sp); c += (float)y0.x;
        p = sigm(l0.y); sa += p; sp = fmaf((float)y0.y, p, sp); c += (float)y0.y;
        p = sigm(l0.z); sa += p; sp = fmaf((float)y0.z, p, sp); c += (float)y0.z;
        p = sigm(l0.w); sa += p; sp = fmaf((float)y0.w, p, sp); c += (float)y0.w;
        p = sigm(l1.x); sa += p; sp = fmaf((float)y1.x, p, sp); c += (float)y1.x;
        p = sigm(l1.y); sa += p; sp = fmaf((float)y1.y, p, sp); c += (float)y1.y;
        p = sigm(l1.z); sa += p; sp = fmaf((float)y1.z, p, sp); c += (float)y1.z;
        p = sigm(l1.w); sa += p; sp = fmaf((float)y1.w, p, sp); c += (float)y1.w;
    }

    // Warp reduce, 3 quantities.
    #pragma unroll
    for (int off = 16; off > 0; off >>= 1) {
        sa += __shfl_down_sync(0xffffffffu, sa, off);
        sp += __shfl_down_sync(0xffffffffu, sp, off);
        c  += __shfl_down_sync(0xffffffffu, c,  off);
    }

    __shared__ float s_a[32], s_p[32], s_c[32];
    if (lid == 0) { s_a[w] = sa; s_p[w] = sp; s_c[w] = c; }
    __syncthreads();

    // Warp 0 finishes: lane = row*4 + warp_in_row partials. Quad-reduce, then
    // per-row loss on quad leaders, then sum the 8 row losses to lane 0.
    if (w == 0) {
        float a  = s_a[lid];
        float pp = s_p[lid];
        float cc = s_c[lid];
        a  += __shfl_down_sync(0xffffffffu, a,  1);
        pp += __shfl_down_sync(0xffffffffu, pp, 1);
        cc += __shfl_down_sync(0xffffffffu, cc, 1);
        a  += __shfl_down_sync(0xffffffffu, a,  2);
        pp += __shfl_down_sync(0xffffffffu, pp, 2);
        cc += __shfl_down_sync(0xffffffffu, cc, 2);

        float rl = 0.f;
        if ((lid & 3) == 0) {
            const float c1 = cc;
            const float c0 = (float)L_COLS - cc;
            const float sneg = a - pp;
            // row loss = c0*c1*gama + c1*sum_neg - c0*sum_pos   (gama = 1)
            rl = fmaf(c1, sneg, fmaf(-c0, pp, c0 * c1));
        }
        rl += __shfl_down_sync(0xffffffffu, rl, 16);
        rl += __shfl_down_sync(0xffffffffu, rl, 8);
        rl += __shfl_down_sync(0xffffffffu, rl, 4);

        if (lid == 0) {
            // Relaxed accumulate (no return needed -> red).
            atomicAdd(&g_accum, rl);

            // acq_rel ticket: orders this block's accum-add before the ticket
            // (release) and, for the winner, makes all other blocks' accum-adds
            // visible (acquire of their releases). No MEMBAR needed.
            unsigned int ticket;
            asm volatile("atom.acq_rel.gpu.global.add.u32 %0, [%1], %2;"
                         : "=r"(ticket) : "l"(&g_ticket), "r"(1u) : "memory");
            if (ticket == NBLOCKS - 1) {
                float tot;
                asm volatile("ld.acquire.gpu.global.f32 %0, [%1];"
                             : "=f"(tot) : "l"(&g_accum) : "memory");
                *out = tot;
                // Rearm for next replay (no concurrent writers remain; next
                // launch is stream-ordered after this kernel retires).
                g_accum  = 0.f;
                g_ticket = 0u;
            }
        }
    }
}

extern "C" void kernel_launch(void* const* d_in, const int* in_sizes, int n_in,
                              void* d_out, int out_size)
{
    const float* logit = (const float*)d_in[0];
    const int*   y     = (const int*)d_in[1];
    float*       out   = (float*)d_out;
    (void)in_sizes; (void)n_in; (void)out_size;

    prl_kernel<<<NBLOCKS, NTHREADS>>>(logit, y, out);
}

// round 5
// speedup vs baseline: 1.2917x; 1.2917x over previous
#include <cuda_runtime.h>

// PairWiseRankingLoss, closed form.
// gama=1, p=sigmoid(x) in (0,1)  =>  1 + p_i - p_j > 0 for every pair, so relu
// never clips and the masked pair-sum factorizes per row:
//   loss_b = n0*n1*gama + n1*sum_{y=0} p - n0*sum_{y=1} p
// Total = sum_b loss_b.
//
// Shape (best measured): 128 CTAs x 256 threads, one row per CTA, 4 elems/thread.
// Cross-block: relaxed float atomicAdd into g_accum, then acq_rel ticket atomic
// (replaces MEMBAR); last ticket holder acquire-loads g_accum, writes out, and
// rearms both globals with plain stores (no concurrent writers remain; next
// graph replay is stream-ordered after this kernel retires).

#define B_ROWS   128
#define L_COLS   1024
#define NTHREADS 256   // 256 threads * 4 elems (float4) = 1024 = one row per block

__device__ float g_accum;           // zero at load; rearmed by last block each launch
__device__ unsigned int g_ticket;   // zero at load; rearmed by last block each launch

__global__ void __launch_bounds__(NTHREADS)
prl_kernel(const float* __restrict__ logit,
           const int*   __restrict__ y,
           float*       __restrict__ out)
{
    const int b   = blockIdx.x;
    const int t   = threadIdx.x;
    const int wid = t >> 5, lid = t & 31;

    // Vectorized coalesced loads: 4 consecutive elements per thread (2x LDG.128).
    const float4 lv = reinterpret_cast<const float4*>(logit + b * L_COLS)[t];
    const int4   yv = reinterpret_cast<const int4*>(y + b * L_COLS)[t];

    // Branchless: sum_all = sum p, sum_pos = sum y*p, cnt = sum y (float, exact).
    float sa = 0.f, sp = 0.f, c = 0.f;
    {
        float p;
        p = 1.f / (1.f + __expf(-lv.x)); sa += p; sp = fmaf((float)yv.x, p, sp); c += (float)yv.x;
        p = 1.f / (1.f + __expf(-lv.y)); sa += p; sp = fmaf((float)yv.y, p, sp); c += (float)yv.y;
        p = 1.f / (1.f + __expf(-lv.z)); sa += p; sp = fmaf((float)yv.z, p, sp); c += (float)yv.z;
        p = 1.f / (1.f + __expf(-lv.w)); sa += p; sp = fmaf((float)yv.w, p, sp); c += (float)yv.w;
    }

    // Warp reduction, 3 quantities interleaved (independent shuffle chains).
    #pragma unroll
    for (int off = 16; off > 0; off >>= 1) {
        sa += __shfl_down_sync(0xffffffffu, sa, off);
        sp += __shfl_down_sync(0xffffffffu, sp, off);
        c  += __shfl_down_sync(0xffffffffu, c,  off);
    }

    __shared__ float s_a[8], s_p[8], s_c[8];
    if (lid == 0) { s_a[wid] = sa; s_p[wid] = sp; s_c[wid] = c; }
    __syncthreads();

    // Warp 0: shuffle-reduce the 8 per-warp partials (depth 3), lane 0 finishes.
    if (wid == 0) {
        float a  = (lid < 8) ? s_a[lid] : 0.f;
        float pp = (lid < 8) ? s_p[lid] : 0.f;
        float cc = (lid < 8) ? s_c[lid] : 0.f;
        #pragma unroll
        for (int off = 4; off > 0; off >>= 1) {
            a  += __shfl_down_sync(0xffffffffu, a,  off);
            pp += __shfl_down_sync(0xffffffffu, pp, off);
            cc += __shfl_down_sync(0xffffffffu, cc, off);
        }
        if (lid == 0) {
            const float c1 = cc;
            const float c0 = (float)L_COLS - cc;
            const float sneg = a - pp;
            // row loss = c0*c1*gama + c1*sum_neg - c0*sum_pos   (gama = 1)
            const float rowloss = fmaf(c1, sneg, fmaf(-c0, pp, c0 * c1));

            // Relaxed accumulate (result unused -> compiles to REDG).
            atomicAdd(&g_accum, rowloss);

            // acq_rel ticket: release-orders this block's accum-add before the
            // ticket; the winner's acquire side makes every other block's
            // accum-add visible. Replaces MEMBAR.GL.
            unsigned int ticket;
            asm volatile("atom.acq_rel.gpu.global.add.u32 %0, [%1], %2;"
                         : "=r"(ticket) : "l"(&g_ticket), "r"(1u) : "memory");
            if (ticket == B_ROWS - 1) {
                float tot;
                asm volatile("ld.acquire.gpu.global.f32 %0, [%1];"
                             : "=f"(tot) : "l"(&g_accum) : "memory");
                *out = tot;
                // Rearm for next graph replay (plain stores; no writers remain).
                g_accum  = 0.f;
                g_ticket = 0u;
            }
        }
    }
}

extern "C" void kernel_launch(void* const* d_in, const int* in_sizes, int n_in,
                              void* d_out, int out_size)
{
    const float* logit = (const float*)d_in[0];
    const int*   y     = (const int*)d_in[1];
    float*       out   = (float*)d_out;
    (void)in_sizes; (void)n_in; (void)out_size;

    prl_kernel<<<B_ROWS, NTHREADS>>>(logit, y, out);
}

// round 6
// speedup vs baseline: 1.3413x; 1.0385x over previous
#include <cuda_runtime.h>

// PairWiseRankingLoss, closed form.
// gama=1, p=sigmoid(x) in (0,1)  =>  1 + p_i - p_j > 0 for every pair, so relu
// never clips and the masked pair-sum factorizes per row:
//   loss_b = n0*n1*gama + n1*sum_{y=0} p - n0*sum_{y=1} p
// Total = sum_b loss_b.
//
// 128 CTAs x 256 threads, one row per CTA, 4 elems/thread (2x LDG.128).
// Cross-block combine: ONE u64 atomicAdd per block into g_acc, packing
//   [63:56] block-arrival count, [55:0] fixed-point (x1024) loss sum.
// The pre-add return value tells each block whether it's last AND the sum of
// all other blocks -- no ticket atomic, no fence, no read-back. Atomics on a
// single address are totally ordered, so no further sync is needed. Integer
// accumulation also makes the output bit-deterministic across replays.

#define B_ROWS   128
#define L_COLS   1024
#define NTHREADS 256   // 256 threads * 4 elems = 1024 = one row per block

#define CNT_SHIFT 56
#define LOW_MASK  ((1ULL << CNT_SHIFT) - 1ULL)
#define FIX_SCALE 1024.0f

__device__ unsigned long long g_acc;   // zero at load; winner rearms each launch

__global__ void __launch_bounds__(NTHREADS)
prl_kernel(const float* __restrict__ logit,
           const int*   __restrict__ y,
           float*       __restrict__ out)
{
    const int b   = blockIdx.x;
    const int t   = threadIdx.x;
    const int wid = t >> 5, lid = t & 31;

    // Vectorized coalesced loads: 4 consecutive elements per thread.
    const float4 lv = reinterpret_cast<const float4*>(logit + b * L_COLS)[t];
    const int4   yv = reinterpret_cast<const int4*>(y + b * L_COLS)[t];

    // Branchless: sa = sum p, sp = sum y*p, cnt = sum y.
    float sa = 0.f, sp = 0.f;
    int cnt;
    {
        float p;
        p = 1.f / (1.f + __expf(-lv.x)); sa += p; sp = fmaf((float)yv.x, p, sp);
        p = 1.f / (1.f + __expf(-lv.y)); sa += p; sp = fmaf((float)yv.y, p, sp);
        p = 1.f / (1.f + __expf(-lv.z)); sa += p; sp = fmaf((float)yv.z, p, sp);
        p = 1.f / (1.f + __expf(-lv.w)); sa += p; sp = fmaf((float)yv.w, p, sp);
        cnt = yv.x + yv.y + yv.z + yv.w;
    }

    // Warp reduce: two interleaved float shuffle chains + one REDUX for the count.
    #pragma unroll
    for (int off = 16; off > 0; off >>= 1) {
        sa += __shfl_down_sync(0xffffffffu, sa, off);
        sp += __shfl_down_sync(0xffffffffu, sp, off);
    }
    cnt = __reduce_add_sync(0xffffffffu, cnt);

    __shared__ float s_a[8], s_p[8];
    __shared__ int   s_c[8];
    if (lid == 0) { s_a[wid] = sa; s_p[wid] = sp; s_c[wid] = cnt; }
    __syncthreads();

    // Warp 0: reduce the 8 per-warp partials, lane 0 finishes.
    if (wid == 0) {
        float a  = (lid < 8) ? s_a[lid] : 0.f;
        float pp = (lid < 8) ? s_p[lid] : 0.f;
        int   cc = (lid < 8) ? s_c[lid] : 0;
        #pragma unroll
        for (int off = 4; off > 0; off >>= 1) {
            a  += __shfl_down_sync(0xffffffffu, a,  off);
            pp += __shfl_down_sync(0xffffffffu, pp, off);
        }
        cc = __reduce_add_sync(0xffffffffu, cc);

        if (lid == 0) {
            const float c1 = (float)cc;
            const float c0 = (float)(L_COLS - cc);
            const float sneg = a - pp;
            // row loss = c0*c1*gama + c1*sum_neg - c0*sum_pos   (gama = 1)
            const float rowloss = fmaf(c1, sneg, fmaf(-c0, pp, c0 * c1));

            // Pack: arrival count in [63:56], fixed-point (x1024) loss in [55:0].
            // rowloss >= 0 and <= ~3e5, so low field stays well under 2^56 even
            // summed over 128 rows (~2^45).
            const unsigned long long contrib =
                (1ULL << CNT_SHIFT) |
                (unsigned long long)__float2ull_rn(rowloss * FIX_SCALE);

            const unsigned long long old = atomicAdd(&g_acc, contrib);
            if ((old >> CNT_SHIFT) == (unsigned long long)(B_ROWS - 1)) {
                // Pre-add value held the other 127 contributions; add ours.
                const unsigned long long tot = (old + contrib) & LOW_MASK;
                *out = (float)((double)tot * (1.0 / (double)FIX_SCALE));
                g_acc = 0ULL;   // rearm for next graph replay (no writers remain)
            }
        }
    }
}

extern "C" void kernel_launch(void* const* d_in, const int* in_sizes, int n_in,
                              void* d_out, int out_size)
{
    const float* logit = (const float*)d_in[0];
    const int*   y     = (const int*)d_in[1];
    float*       out   = (float*)d_out;
    (void)in_sizes; (void)n_in; (void)out_size;

    prl_kernel<<<B_ROWS, NTHREADS>>>(logit, y, out);
}